// round 1
// baseline (speedup 1.0000x reference)
#include <cuda_runtime.h>

// ---------------------------------------------------------------------------
// GCN 5-layer forward, max-aggregation, on GB300.
// Strategy: build CSR (by destination) once, fold dinv into GEMM epilogue so
// aggregation is an atomic-free gather-max:  agg[c] = dinv[c] * max(y[c], y[nbr...])
// ---------------------------------------------------------------------------

#define MAXN 200000
#define MAXE 6400000
#define MAXCHUNK 64   // ceil(200000/4096)=49

__device__ int   g_cnt[MAXN];
__device__ int   g_cur[MAXN];
__device__ float g_dinv[MAXN];
__device__ int   g_off[MAXN + 1];
__device__ int   g_csr[MAXE];
__device__ int   g_bsums[MAXCHUNK];
__device__ int   g_boff[MAXCHUNK];
__device__ float g_y[(size_t)MAXN * 24];
__device__ float g_h[(size_t)MAXN * 24];

// ---------------- preprocessing ----------------

__global__ void k_init(int n, int nchunks) {
    int i = blockIdx.x * blockDim.x + threadIdx.x;
    if (i < n) { g_cnt[i] = 0; g_cur[i] = 0; }
    if (i < nchunks) g_bsums[i] = 0;
}

__global__ void k_count(const int* __restrict__ col, int e) {
    int i = blockIdx.x * blockDim.x + threadIdx.x;
    if (i < e) atomicAdd(&g_cnt[col[i]], 1);
}

__global__ void k_dinv(int n) {
    int i = blockIdx.x * blockDim.x + threadIdx.x;
    if (i < n) g_dinv[i] = rsqrtf((float)g_cnt[i] + 1.0f);  // +1 self loop
}

// per-4096-chunk sums (warp reduce + one atomic per warp)
__global__ void k_scan1(int n) {
    int i = blockIdx.x * blockDim.x + threadIdx.x;
    int v = (i < n) ? g_cnt[i] : 0;
    #pragma unroll
    for (int o = 16; o; o >>= 1) v += __shfl_down_sync(0xffffffffu, v, o);
    if ((threadIdx.x & 31) == 0) atomicAdd(&g_bsums[blockIdx.x >> 2], v);
}

__global__ void k_scan2(int nchunks, int n) {
    if (threadIdx.x == 0 && blockIdx.x == 0) {
        int s = 0;
        for (int i = 0; i < nchunks; i++) { g_boff[i] = s; s += g_bsums[i]; }
        g_off[n] = s;
    }
}

// block-level exclusive scan within each 4096 chunk, + chunk offset
__global__ void k_scan3(int n) {
    __shared__ int wsum[32];
    int base = blockIdx.x * 4096 + threadIdx.x * 4;
    int v[4]; int s = 0;
    #pragma unroll
    for (int j = 0; j < 4; j++) { int idx = base + j; v[j] = (idx < n) ? g_cnt[idx] : 0; s += v[j]; }
    int lane = threadIdx.x & 31, w = threadIdx.x >> 5;
    int inc = s;
    #pragma unroll
    for (int o = 1; o < 32; o <<= 1) { int t = __shfl_up_sync(0xffffffffu, inc, o); if (lane >= o) inc += t; }
    if (lane == 31) wsum[w] = inc;
    __syncthreads();
    if (w == 0) {
        int ws = wsum[lane];
        #pragma unroll
        for (int o = 1; o < 32; o <<= 1) { int t = __shfl_up_sync(0xffffffffu, ws, o); if (lane >= o) ws += t; }
        wsum[lane] = ws;
    }
    __syncthreads();
    int ex = inc - s + (w ? wsum[w - 1] : 0) + g_boff[blockIdx.x];
    #pragma unroll
    for (int j = 0; j < 4; j++) { int idx = base + j; if (idx < n) g_off[idx] = ex; ex += v[j]; }
}

__global__ void k_fill(const int* __restrict__ row, const int* __restrict__ col, int e) {
    int i = blockIdx.x * blockDim.x + threadIdx.x;
    if (i >= e) return;
    int c = col[i];
    int p = g_off[c] + atomicAdd(&g_cur[c], 1);
    g_csr[p] = row[i];
}

// ---------------- per-layer kernels ----------------

// y = dinv ⊙ (src @ W), W staged to smem, thread-per-row
template <int DIN, int DOUT, bool FROMX>
__global__ void k_gemm(const float* __restrict__ xin, const float* __restrict__ W, int n) {
    __shared__ float Ws[DIN * DOUT];
    for (int i = threadIdx.x; i < DIN * DOUT; i += blockDim.x) Ws[i] = W[i];
    __syncthreads();
    int r = blockIdx.x * blockDim.x + threadIdx.x;
    if (r >= n) return;
    const float* src = FROMX ? (xin + (size_t)r * DIN) : (g_h + (size_t)r * DIN);
    float acc[DOUT];
    #pragma unroll
    for (int j = 0; j < DOUT; j++) acc[j] = 0.f;
    if constexpr (DIN % 4 == 0) {
        const float4* s4 = reinterpret_cast<const float4*>(src);
        #pragma unroll 4
        for (int k4 = 0; k4 < DIN / 4; k4++) {
            float4 xv = s4[k4];
            #pragma unroll
            for (int j = 0; j < DOUT; j++)
                acc[j] += xv.x * Ws[(4 * k4 + 0) * DOUT + j]
                        + xv.y * Ws[(4 * k4 + 1) * DOUT + j]
                        + xv.z * Ws[(4 * k4 + 2) * DOUT + j]
                        + xv.w * Ws[(4 * k4 + 3) * DOUT + j];
        }
    } else {
        #pragma unroll
        for (int k = 0; k < DIN; k++) {
            float xv = src[k];
            #pragma unroll
            for (int j = 0; j < DOUT; j++) acc[j] += xv * Ws[k * DOUT + j];
        }
    }
    float dv = g_dinv[r];
    #pragma unroll
    for (int j = 0; j < DOUT; j++) g_y[(size_t)r * DOUT + j] = dv * acc[j];
}

// h[c,f] = tanh( dinv[c] * max(y[c,f], max_{r in CSR[c]} y[r,f]) + b[f] )
// G threads per node (G = pow2 >= D), lane = feature.
template <int D, int G>
__global__ void k_agg(const float* __restrict__ bias, int n) {
    int t = blockIdx.x * blockDim.x + threadIdx.x;
    int node = t / G;
    int f = t & (G - 1);
    if (node >= n) return;
    int s = g_off[node], e2 = g_off[node + 1];
    float m = 0.f;
    if (f < D) m = g_y[(size_t)node * D + f];   // self-loop message
    #pragma unroll 4
    for (int i = s; i < e2; i++) {
        int r = g_csr[i];
        if (f < D) m = fmaxf(m, g_y[(size_t)r * D + f]);
    }
    if (f < D) g_h[(size_t)node * D + f] = tanhf(g_dinv[node] * m + bias[f]);
}

__global__ void k_cls(const float* __restrict__ Wc, const float* __restrict__ bc,
                      float* __restrict__ out, int n, int write_h) {
    int i = blockIdx.x * blockDim.x + threadIdx.x;
    if (i >= n) return;
    float h0 = g_h[(size_t)i * 2], h1 = g_h[(size_t)i * 2 + 1];
    #pragma unroll
    for (int k = 0; k < 4; k++)
        out[(size_t)i * 4 + k] = h0 * Wc[k] + h1 * Wc[4 + k] + bc[k];
    if (write_h) {
        out[(size_t)4 * n + (size_t)i * 2]     = h0;
        out[(size_t)4 * n + (size_t)i * 2 + 1] = h1;
    }
}

// ---------------- launch ----------------

extern "C" void kernel_launch(void* const* d_in, const int* in_sizes, int n_in,
                              void* d_out, int out_size) {
    const float* x  = (const float*)d_in[0];
    const int*   ei = (const int*)d_in[1];
    const float* W1 = (const float*)d_in[2];  const float* b1 = (const float*)d_in[3];
    const float* W2 = (const float*)d_in[4];  const float* b2 = (const float*)d_in[5];
    const float* W3 = (const float*)d_in[6];  const float* b3 = (const float*)d_in[7];
    const float* W4 = (const float*)d_in[8];  const float* b4 = (const float*)d_in[9];
    const float* W5 = (const float*)d_in[10]; const float* b5 = (const float*)d_in[11];
    const float* Wc = (const float*)d_in[12]; const float* bc = (const float*)d_in[13];

    int n = in_sizes[0] / 128;
    int e = in_sizes[1] / 2;
    const int* row = ei;
    const int* col = ei + e;

    const int TB = 256;
    int nchunks = (n + 4095) / 4096;

    k_init <<<(n + TB - 1) / TB, TB>>>(n, nchunks);
    k_count<<<(e + TB - 1) / TB, TB>>>(col, e);
    k_dinv <<<(n + TB - 1) / TB, TB>>>(n);
    k_scan1<<<(n + 1023) / 1024, 1024>>>(n);
    k_scan2<<<1, 32>>>(nchunks, n);
    k_scan3<<<nchunks, 1024>>>(n);
    k_fill <<<(e + TB - 1) / TB, TB>>>(row, col, e);

    // layer 1: 128 -> 24
    k_gemm<128, 24, true ><<<(n + TB - 1) / TB, TB>>>(x, W1, n);
    k_agg <24, 32><<<((size_t)n * 32 + TB - 1) / TB, TB>>>(b1, n);
    // layer 2: 24 -> 12
    k_gemm<24, 12, false><<<(n + TB - 1) / TB, TB>>>(nullptr, W2, n);
    k_agg <12, 16><<<((size_t)n * 16 + TB - 1) / TB, TB>>>(b2, n);
    // layer 3: 12 -> 6
    k_gemm<12, 6, false><<<(n + TB - 1) / TB, TB>>>(nullptr, W3, n);
    k_agg <6, 8><<<((size_t)n * 8 + TB - 1) / TB, TB>>>(b3, n);
    // layer 4: 6 -> 4
    k_gemm<6, 4, false><<<(n + TB - 1) / TB, TB>>>(nullptr, W4, n);
    k_agg <4, 4><<<((size_t)n * 4 + TB - 1) / TB, TB>>>(b4, n);
    // layer 5: 4 -> 2
    k_gemm<4, 2, false><<<(n + TB - 1) / TB, TB>>>(nullptr, W5, n);
    k_agg <2, 2><<<((size_t)n * 2 + TB - 1) / TB, TB>>>(b5, n);

    int write_h = (out_size >= 6 * n) ? 1 : 0;
    k_cls<<<(n + TB - 1) / TB, TB>>>(Wc, bc, (float*)d_out, n, write_h);
}